// round 6
// baseline (speedup 1.0000x reference)
#include <cuda_runtime.h>
#include <math.h>
#include <stdint.h>

// Problem constants
// B=2, T=16, S=512, D=512, H=8, hd=64  -> M = B*T*S = 16384 rows
#define M_ROWS 16384
#define DIM 512
#define NHEAD 8
#define HDIM 64
#define TPAD 68          // padded tile row (64+4)
#define TILE_F (64 * TPAD)

// GEMM tiling
#define BM 128
#define BN 128
#define BK 16
#define KPAD 136         // smem row stride: 136 mod 32 = 8 banks -> bank = 8*tg + g
                         // is a perfect 32-bank permutation (conflict-free LDS)

// Scratch (device globals: allocation-guard safe). 4 x 32 MB.
__device__ float g_Q[(size_t)M_ROWS * DIM];
__device__ float g_K[(size_t)M_ROWS * DIM];
__device__ float g_V[(size_t)M_ROWS * DIM];
__device__ float g_att[(size_t)M_ROWS * DIM];

// ---------------------------------------------------------------------------
// 3xTF32 helpers
// ---------------------------------------------------------------------------
__device__ __forceinline__ void f32_split_tf32(float x, uint32_t& hi, uint32_t& lo) {
    asm("cvt.rna.tf32.f32 %0, %1;" : "=r"(hi) : "f"(x));
    float r = x - __uint_as_float(hi);
    asm("cvt.rna.tf32.f32 %0, %1;" : "=r"(lo) : "f"(r));
}

__device__ __forceinline__ void mma_tf32(float* d, const uint32_t* a, const uint32_t* b) {
    asm volatile(
        "mma.sync.aligned.m16n8k8.row.col.f32.tf32.tf32.f32 "
        "{%0,%1,%2,%3}, {%4,%5,%6,%7}, {%8,%9}, {%0,%1,%2,%3};"
        : "+f"(d[0]), "+f"(d[1]), "+f"(d[2]), "+f"(d[3])
        : "r"(a[0]), "r"(a[1]), "r"(a[2]), "r"(a[3]), "r"(b[0]), "r"(b[1]));
}

// ---------------------------------------------------------------------------
// GEMM + bias via 3xTF32 tensor-core mma: Y[M,512] = X[M,512] @ W[512,512] + b
// CTA 128x128, BK=16, 256 threads = 8 warps (2m x 4n), warp tile 64x32.
// Double-buffered smem (one barrier per k-chunk), global->reg prefetch.
// A smem transposed [k][m] (stride KPAD), B smem [k][n] (stride KPAD).
// A loader: arow=tid&127, ac=(tid>>7)*8 -> STS banks follow consecutive arow
// (conflict-free) and each LDG touches a contiguous 32B sector per row.
// Precision: hi/lo tf32 split, D += Ahi*Bhi + Ahi*Blo + Alo*Bhi  (~fp32).
// ---------------------------------------------------------------------------
__global__ __launch_bounds__(256) void gemm_tf32_kernel(
    const float* __restrict__ X, const float* __restrict__ W,
    const float* __restrict__ bias, float* __restrict__ Y)
{
    __shared__ __align__(16) float As[2][BK * KPAD];
    __shared__ __align__(16) float Bs[2][BK * KPAD];

    const int tid  = threadIdx.x;
    const int wid  = tid >> 5;
    const int lane = tid & 31;
    const int g    = lane >> 2;         // 0..7
    const int tg   = lane & 3;          // 0..3
    const int wm   = (wid >> 2) * 64;   // warp m offset: 0 / 64
    const int wn   = (wid & 3) * 32;    // warp n offset: 0/32/64/96
    const int n0   = blockIdx.x * BN;
    const int m0   = blockIdx.y * BM;

    // A loader: 128 rows x 16 cols; thread -> (row = tid&127, col8 = (tid>>7)*8)
    const int arow = tid & 127;
    const int ac8  = (tid >> 7) * 8;
    // B loader: 16 rows x 128 cols; thread -> (row = tid>>5 and +8, col4 = (tid&31)*4)
    const int brow = tid >> 5;
    const int bc4  = (tid & 31) * 4;

    const float* Xa = X + (size_t)(m0 + arow) * DIM + ac8;
    const float* Wa = W + (size_t)brow * DIM + n0 + bc4;
    const float* Wb = W + (size_t)(brow + 8) * DIM + n0 + bc4;

    float acc[4][4][4];   // [mf][nf][c]
    #pragma unroll
    for (int i = 0; i < 4; i++)
        #pragma unroll
        for (int j = 0; j < 4; j++)
            #pragma unroll
            for (int c = 0; c < 4; c++)
                acc[i][j][c] = 0.f;

    // prologue: load chunk 0
    float4 pa0 = *reinterpret_cast<const float4*>(Xa);
    float4 pa1 = *reinterpret_cast<const float4*>(Xa + 4);
    float4 pb0 = *reinterpret_cast<const float4*>(Wa);
    float4 pb1 = *reinterpret_cast<const float4*>(Wb);
    {
        float* A0 = As[0];
        A0[(ac8 + 0) * KPAD + arow] = pa0.x;
        A0[(ac8 + 1) * KPAD + arow] = pa0.y;
        A0[(ac8 + 2) * KPAD + arow] = pa0.z;
        A0[(ac8 + 3) * KPAD + arow] = pa0.w;
        A0[(ac8 + 4) * KPAD + arow] = pa1.x;
        A0[(ac8 + 5) * KPAD + arow] = pa1.y;
        A0[(ac8 + 6) * KPAD + arow] = pa1.z;
        A0[(ac8 + 7) * KPAD + arow] = pa1.w;
        *reinterpret_cast<float4*>(&Bs[0][brow * KPAD + bc4]) = pb0;
        *reinterpret_cast<float4*>(&Bs[0][(brow + 8) * KPAD + bc4]) = pb1;
    }
    __syncthreads();

    int buf = 0;
    for (int kk = 0; kk < DIM; kk += BK) {
        const bool more = (kk + BK < DIM);
        if (more) {
            pa0 = *reinterpret_cast<const float4*>(Xa + kk + BK);
            pa1 = *reinterpret_cast<const float4*>(Xa + kk + BK + 4);
            pb0 = *reinterpret_cast<const float4*>(Wa + (size_t)(kk + BK) * DIM);
            pb1 = *reinterpret_cast<const float4*>(Wb + (size_t)(kk + BK) * DIM);
        }

        const float* Ab = As[buf];
        const float* Bb = Bs[buf];
        #pragma unroll
        for (int ks = 0; ks < BK; ks += 8) {
            // B fragments: fp32 load + split (shared across all mf)
            uint32_t bhi[4][2], blo[4][2];
            #pragma unroll
            for (int nf = 0; nf < 4; nf++) {
                const int ncol = wn + nf * 8 + g;
                float b0 = Bb[(ks + tg) * KPAD + ncol];
                float b1 = Bb[(ks + tg + 4) * KPAD + ncol];
                f32_split_tf32(b0, bhi[nf][0], blo[nf][0]);
                f32_split_tf32(b1, bhi[nf][1], blo[nf][1]);
            }
            // A fragments per mf, then 12 mma
            #pragma unroll
            for (int mf = 0; mf < 4; mf++) {
                const int mrow = wm + mf * 16 + g;
                float a0 = Ab[(ks + tg) * KPAD + mrow];
                float a1 = Ab[(ks + tg) * KPAD + mrow + 8];
                float a2 = Ab[(ks + tg + 4) * KPAD + mrow];
                float a3 = Ab[(ks + tg + 4) * KPAD + mrow + 8];
                uint32_t ahi[4], alo[4];
                f32_split_tf32(a0, ahi[0], alo[0]);
                f32_split_tf32(a1, ahi[1], alo[1]);
                f32_split_tf32(a2, ahi[2], alo[2]);
                f32_split_tf32(a3, ahi[3], alo[3]);
                #pragma unroll
                for (int nf = 0; nf < 4; nf++) {
                    mma_tf32(acc[mf][nf], ahi, bhi[nf]);
                    mma_tf32(acc[mf][nf], ahi, blo[nf]);
                    mma_tf32(acc[mf][nf], alo, bhi[nf]);
                }
            }
        }

        if (more) {
            float* An = As[buf ^ 1];
            An[(ac8 + 0) * KPAD + arow] = pa0.x;
            An[(ac8 + 1) * KPAD + arow] = pa0.y;
            An[(ac8 + 2) * KPAD + arow] = pa0.z;
            An[(ac8 + 3) * KPAD + arow] = pa0.w;
            An[(ac8 + 4) * KPAD + arow] = pa1.x;
            An[(ac8 + 5) * KPAD + arow] = pa1.y;
            An[(ac8 + 6) * KPAD + arow] = pa1.z;
            An[(ac8 + 7) * KPAD + arow] = pa1.w;
            *reinterpret_cast<float4*>(&Bs[buf ^ 1][brow * KPAD + bc4]) = pb0;
            *reinterpret_cast<float4*>(&Bs[buf ^ 1][(brow + 8) * KPAD + bc4]) = pb1;
            __syncthreads();
            buf ^= 1;
        }
    }

    // Epilogue: D layout c0=(g,2t) c1=(g,2t+1) c2=(g+8,2t) c3=(g+8,2t+1)
    #pragma unroll
    for (int nf = 0; nf < 4; nf++) {
        const int col = n0 + wn + nf * 8 + 2 * tg;
        const float2 bv = *reinterpret_cast<const float2*>(bias + col);
        #pragma unroll
        for (int mf = 0; mf < 4; mf++) {
            const int row0 = m0 + wm + mf * 16 + g;
            float2 o0 = {acc[mf][nf][0] + bv.x, acc[mf][nf][1] + bv.y};
            float2 o1 = {acc[mf][nf][2] + bv.x, acc[mf][nf][3] + bv.y};
            *reinterpret_cast<float2*>(Y + (size_t)row0 * DIM + col) = o0;
            *reinterpret_cast<float2*>(Y + (size_t)(row0 + 8) * DIM + col) = o1;
        }
    }
}

// ---------------------------------------------------------------------------
// Attention: per (b,t,h, q-tile of 64 rows).  (unchanged from R5 — kept FFMA
// for diagnostic separability vs the tf32 GEMM path)
//   scores = (Q Kt)/8 * mw[h] + ts[t,h];  p = sigmoid((s-max)*5); attn = p/(sum+1e-8)
//   out = attn @ V
// All 512 scores per row live in registers (sc[8][4][4] per thread).
// Dynamic smem, double-buffered chunk tiles: one barrier per chunk in both
// GEMM phases. Layout: [ smA0 | smA1 | smB0 | smB1 ], each 64*TPAD floats.
// ---------------------------------------------------------------------------
extern __shared__ float dynsm[];

__global__ __launch_bounds__(256) void attn_kernel(
    const float* __restrict__ Q, const float* __restrict__ Km,
    const float* __restrict__ Vm, float* __restrict__ att,
    const float* __restrict__ MW, const float* __restrict__ TSy,
    const int* __restrict__ qm_p, const int* __restrict__ km_p)
{
    float* const smA[2] = {dynsm, dynsm + TILE_F};
    float* const smB[2] = {dynsm + 2 * TILE_F, dynsm + 3 * TILE_F};

    const int tid = threadIdx.x;
    const int tx = tid & 15;   // key/d sub-tile
    const int ty = tid >> 4;   // query sub-tile
    const int qt = blockIdx.x;     // 0..7
    const int h  = blockIdx.y;     // 0..7
    const int bt = blockIdx.z;     // 0..31  (= b*16 + t)
    const int t  = bt & 15;

    const float* Qb = Q  + ((size_t)bt * 512 + qt * 64) * DIM + h * HDIM;
    const float* Kb = Km + (size_t)bt * 512 * DIM + h * HDIM;
    const float* Vb = Vm + (size_t)bt * 512 * DIM + h * HDIM;

    const int lr = tid >> 2;          // 0..63
    const int lc = (tid & 3) * 16;    // 0,16,32,48

    // --- Prologue: Q^T into smA0, K chunk 0 (transposed) into smB0 ---
    #pragma unroll
    for (int u = 0; u < 4; u++) {
        float4 v = *reinterpret_cast<const float4*>(Qb + (size_t)lr * DIM + lc + u * 4);
        smA[0][(lc + u * 4 + 0) * TPAD + lr] = v.x;
        smA[0][(lc + u * 4 + 1) * TPAD + lr] = v.y;
        smA[0][(lc + u * 4 + 2) * TPAD + lr] = v.z;
        smA[0][(lc + u * 4 + 3) * TPAD + lr] = v.w;
    }
    float4 pf[4];
    #pragma unroll
    for (int u = 0; u < 4; u++)
        pf[u] = *reinterpret_cast<const float4*>(Kb + (size_t)lr * DIM + lc + u * 4);
    #pragma unroll
    for (int u = 0; u < 4; u++) {
        smB[0][(lc + u * 4 + 0) * TPAD + lr] = pf[u].x;
        smB[0][(lc + u * 4 + 1) * TPAD + lr] = pf[u].y;
        smB[0][(lc + u * 4 + 2) * TPAD + lr] = pf[u].z;
        smB[0][(lc + u * 4 + 3) * TPAD + lr] = pf[u].w;
    }
    __syncthreads();

    float sc[8][4][4];
    #pragma unroll
    for (int c = 0; c < 8; c++)
        #pragma unroll
        for (int i = 0; i < 4; i++)
            #pragma unroll
            for (int j = 0; j < 4; j++)
                sc[c][i][j] = 0.f;

    // --- Phase 1: scores = Q @ K^T, double-buffered K chunks ---
    #pragma unroll
    for (int c = 0; c < 8; c++) {
        if (c + 1 < 8) {
            #pragma unroll
            for (int u = 0; u < 4; u++)
                pf[u] = *reinterpret_cast<const float4*>(
                    Kb + (size_t)((c + 1) * 64 + lr) * DIM + lc + u * 4);
        }
        const float* Bb = smB[c & 1];
        #pragma unroll 4
        for (int p = 0; p < 64; p++) {
            float4 a4 = *reinterpret_cast<const float4*>(&smA[0][p * TPAD + ty * 4]);
            float4 b4 = *reinterpret_cast<const float4*>(&Bb[p * TPAD + tx * 4]);
            float a_[4] = {a4.x, a4.y, a4.z, a4.w};
            float b_[4] = {b4.x, b4.y, b4.z, b4.w};
            #pragma unroll
            for (int i = 0; i < 4; i++)
                #pragma unroll
                for (int j = 0; j < 4; j++)
                    sc[c][i][j] += a_[i] * b_[j];
        }
        if (c + 1 < 8) {
            float* Bn = smB[(c + 1) & 1];
            #pragma unroll
            for (int u = 0; u < 4; u++) {
                Bn[(lc + u * 4 + 0) * TPAD + lr] = pf[u].x;
                Bn[(lc + u * 4 + 1) * TPAD + lr] = pf[u].y;
                Bn[(lc + u * 4 + 2) * TPAD + lr] = pf[u].z;
                Bn[(lc + u * 4 + 3) * TPAD + lr] = pf[u].w;
            }
            __syncthreads();
        }
    }

    // --- Phase 2: sigmoid-softmax over 512 keys per query row ---
    const int qm = *qm_p;
    const int km = *km_p;
    const float coef  = MW[qm * NHEAD + h] * MW[km * NHEAD + h] * 0.125f; // /sqrt(64)
    const float tbias = TSy[t * NHEAD + h];

    #pragma unroll
    for (int i = 0; i < 4; i++) {
        float m = -1e30f;
        #pragma unroll
        for (int c = 0; c < 8; c++)
            #pragma unroll
            for (int j = 0; j < 4; j++) {
                sc[c][i][j] = sc[c][i][j] * coef + tbias;
                m = fmaxf(m, sc[c][i][j]);
            }
        #pragma unroll
        for (int o = 8; o >= 1; o >>= 1)
            m = fmaxf(m, __shfl_xor_sync(0xffffffffu, m, o));
        float s = 0.f;
        #pragma unroll
        for (int c = 0; c < 8; c++)
            #pragma unroll
            for (int j = 0; j < 4; j++) {
                float pv = 1.0f / (1.0f + expf(-5.0f * (sc[c][i][j] - m)));
                sc[c][i][j] = pv;
                s += pv;
            }
        #pragma unroll
        for (int o = 8; o >= 1; o >>= 1)
            s += __shfl_xor_sync(0xffffffffu, s, o);
        const float inv = 1.0f / (s + 1e-8f);
        #pragma unroll
        for (int c = 0; c < 8; c++)
            #pragma unroll
            for (int j = 0; j < 4; j++)
                sc[c][i][j] *= inv;
    }

    // --- Phase 3: out = attn @ V, double-buffered P and V chunks ---
    #pragma unroll
    for (int u = 0; u < 4; u++)
        pf[u] = *reinterpret_cast<const float4*>(Vb + (size_t)lr * DIM + lc + u * 4);
    __syncthreads();   // all phase-1 reads of smA/smB complete before overwrite
    #pragma unroll
    for (int i = 0; i < 4; i++)
        #pragma unroll
        for (int j = 0; j < 4; j++)
            smA[0][(ty * 4 + i) * TPAD + tx * 4 + j] = sc[0][i][j];
    #pragma unroll
    for (int u = 0; u < 4; u++)
        *reinterpret_cast<float4*>(&smB[0][lr * TPAD + lc + u * 4]) = pf[u];
    __syncthreads();

    float out[4][4] = {};
    #pragma unroll
    for (int c = 0; c < 8; c++) {
        if (c + 1 < 8) {
            #pragma unroll
            for (int u = 0; u < 4; u++)
                pf[u] = *reinterpret_cast<const float4*>(
                    Vb + (size_t)((c + 1) * 64 + lr) * DIM + lc + u * 4);
        }
        const float* Ab = smA[c & 1];
        const float* Bb = smB[c & 1];
        #pragma unroll 4
        for (int p = 0; p < 64; p++) {
            float a_[4];
            #pragma unroll
            for (int i = 0; i < 4; i++) a_[i] = Ab[(ty * 4 + i) * TPAD + p];
            float4 b4 = *reinterpret_cast<const float4*>(&Bb[p * TPAD + tx * 4]);
            float b_[4] = {b4.x, b4.y, b4.z, b4.w};
            #pragma unroll
            for (int i = 0; i < 4; i++)
                #pragma unroll
                for (int j = 0; j < 4; j++)
                    out[i][j] += a_[i] * b_[j];
        }
        if (c + 1 < 8) {
            float* An = smA[(c + 1) & 1];
            float* Bn = smB[(c + 1) & 1];
            #pragma unroll
            for (int i = 0; i < 4; i++)
                #pragma unroll
                for (int j = 0; j < 4; j++)
                    An[(ty * 4 + i) * TPAD + tx * 4 + j] = sc[c + 1][i][j];
            #pragma unroll
            for (int u = 0; u < 4; u++)
                *reinterpret_cast<float4*>(&Bn[lr * TPAD + lc + u * 4]) = pf[u];
            __syncthreads();
        }
    }

    // Store attended tile
    #pragma unroll
    for (int i = 0; i < 4; i++) {
        float4 o = {out[i][0], out[i][1], out[i][2], out[i][3]};
        *reinterpret_cast<float4*>(
            att + ((size_t)bt * 512 + qt * 64 + ty * 4 + i) * DIM + h * HDIM + tx * 4) = o;
    }
}

// ---------------------------------------------------------------------------
// Launch
// Inputs (metadata order):
//  0 query_spikes [2,16,512,512] f32   1 key_spikes   2 value_spikes
//  3 Wq [512,512]  4 bq [512]  5 Wk  6 bk  7 Wv  8 bv  9 Wo  10 bo
//  11 modality_weights [2,8]  12 temporal_sync [16,8]
//  13 query_modality (int)   14 key_modality (int)
// Output: [2,16,512,512] f32
// ---------------------------------------------------------------------------
extern "C" void kernel_launch(void* const* d_in, const int* in_sizes, int n_in,
                              void* d_out, int out_size)
{
    (void)in_sizes; (void)n_in; (void)out_size;

    const float* qs = (const float*)d_in[0];
    const float* ks = (const float*)d_in[1];
    const float* vs = (const float*)d_in[2];
    const float* Wq = (const float*)d_in[3];
    const float* bq = (const float*)d_in[4];
    const float* Wk = (const float*)d_in[5];
    const float* bk = (const float*)d_in[6];
    const float* Wv = (const float*)d_in[7];
    const float* bv = (const float*)d_in[8];
    const float* Wo = (const float*)d_in[9];
    const float* bo = (const float*)d_in[10];
    const float* MW = (const float*)d_in[11];
    const float* TSy = (const float*)d_in[12];
    const int* qm = (const int*)d_in[13];
    const int* km = (const int*)d_in[14];
    float* out = (float*)d_out;

    // Device-global scratch pointers (symbol lookup: not a stream op, capture-safe)
    void *pQ, *pK, *pV, *pA;
    cudaGetSymbolAddress(&pQ, g_Q);
    cudaGetSymbolAddress(&pK, g_K);
    cudaGetSymbolAddress(&pV, g_V);
    cudaGetSymbolAddress(&pA, g_att);
    float* gQ = (float*)pQ;
    float* gK = (float*)pK;
    float* gV = (float*)pV;
    float* gA = (float*)pA;

    // Unconditional (idempotent, host-side, not a stream op — capture-safe;
    // no static guard so every call does identical work per the harness rules)
    const int attn_smem = 4 * TILE_F * sizeof(float);   // 69632 B
    cudaFuncSetAttribute(attn_kernel,
                         cudaFuncAttributeMaxDynamicSharedMemorySize, attn_smem);

    dim3 gemm_grid(DIM / BN, M_ROWS / BM);   // (4, 128)
    dim3 attn_grid(8, NHEAD, 32);            // q-tiles, heads, b*t

    gemm_tf32_kernel<<<gemm_grid, 256>>>(qs, Wq, bq, gQ);
    gemm_tf32_kernel<<<gemm_grid, 256>>>(ks, Wk, bk, gK);
    gemm_tf32_kernel<<<gemm_grid, 256>>>(vs, Wv, bv, gV);
    attn_kernel<<<attn_grid, 256, attn_smem>>>(gQ, gK, gV, gA, MW, TSy, qm, km);
    gemm_tf32_kernel<<<gemm_grid, 256>>>(gA, Wo, bo, out);
}

// round 16
// speedup vs baseline: 1.4657x; 1.4657x over previous
#include <cuda_runtime.h>
#include <cuda_fp16.h>
#include <math.h>
#include <stdint.h>

// Problem constants
// B=2, T=16, S=512, D=512, H=8, hd=64  -> M = B*T*S = 16384 rows
#define M_ROWS 16384
#define DIM 512
#define NHEAD 8
#define HDIM 64
#define TPAD 68          // attn padded tile row (64+4) — unchanged (verified R6)
#define TILE_F (64 * TPAD)

// GEMM tiling
#define BM 128
#define BN 128
#define BK 16
#define KPAD 132         // 132 mod 32 = 4 banks/row: k rows {2t,2t+1,2t+8,2t+9}
                         // give bank = 8t (+4) + g -> perfect 32-bank permutation
                         // for the fp16 k-pair fragment loads (conflict-free)

// Scratch (device globals: allocation-guard safe). 4 x 32 MB.
__device__ float g_Q[(size_t)M_ROWS * DIM];
__device__ float g_K[(size_t)M_ROWS * DIM];
__device__ float g_V[(size_t)M_ROWS * DIM];
__device__ float g_att[(size_t)M_ROWS * DIM];

// ---------------------------------------------------------------------------
// fp16 hi/lo split helpers (3-term error compensation, ~2^-22 residual)
// ---------------------------------------------------------------------------
__device__ __forceinline__ void split2_f16(float x0, float x1,
                                           uint32_t& hi, uint32_t& lo) {
    __half h0 = __float2half_rn(x0);
    __half h1 = __float2half_rn(x1);
    __half l0 = __float2half_rn(x0 - __half2float(h0));
    __half l1 = __float2half_rn(x1 - __half2float(h1));
    __half2 H = __halves2half2(h0, h1);
    __half2 L = __halves2half2(l0, l1);
    hi = *reinterpret_cast<uint32_t*>(&H);
    lo = *reinterpret_cast<uint32_t*>(&L);
}

// m16n8k16 fp16 mma, fp32 accum. A row-major frag (4 regs), B col-major (2 regs).
__device__ __forceinline__ void mma_f16(float* d, const uint32_t* a, const uint32_t* b) {
    asm volatile(
        "mma.sync.aligned.m16n8k16.row.col.f32.f16.f16.f32 "
        "{%0,%1,%2,%3}, {%4,%5,%6,%7}, {%8,%9}, {%0,%1,%2,%3};"
        : "+f"(d[0]), "+f"(d[1]), "+f"(d[2]), "+f"(d[3])
        : "r"(a[0]), "r"(a[1]), "r"(a[2]), "r"(a[3]), "r"(b[0]), "r"(b[1]));
}

// ---------------------------------------------------------------------------
// GEMM + bias via 3x-fp16-split m16n8k16 mma: Y = X @ W + b.
// CTA 128x128, BK=16, 256 threads = 8 warps (2m x 4n), warp tile 64x32.
// Same structure as the verified R6 tf32 kernel (double-buffered smem,
// one barrier/chunk, reg prefetch); HMMA count halved (48 vs 96 per chunk)
// to attack the measured ~16cyc/instr dispatch limit of the legacy mma path.
// Fragment map (m16n8k16, g=lane>>2, t=lane&3):
//   A: r0={A[g][2t],A[g][2t+1]} r1={A[g+8][2t],A[g+8][2t+1]}
//      r2={A[g][2t+8],A[g][2t+9]} r3={A[g+8][2t+8],A[g+8][2t+9]}
//   B: r0={B[2t][n],B[2t+1][n]}  r1={B[2t+8][n],B[2t+9][n]}
//   C: c0=(g,2t) c1=(g,2t+1) c2=(g+8,2t) c3=(g+8,2t+1)   (same as tf32 k8)
// ---------------------------------------------------------------------------
__global__ __launch_bounds__(256) void gemm_f16split_kernel(
    const float* __restrict__ X, const float* __restrict__ W,
    const float* __restrict__ bias, float* __restrict__ Y)
{
    __shared__ __align__(16) float As[2][BK * KPAD];
    __shared__ __align__(16) float Bs[2][BK * KPAD];

    const int tid  = threadIdx.x;
    const int wid  = tid >> 5;
    const int lane = tid & 31;
    const int g    = lane >> 2;         // 0..7
    const int tg   = lane & 3;          // 0..3
    const int wm   = (wid >> 2) * 64;   // warp m offset: 0 / 64
    const int wn   = (wid & 3) * 32;    // warp n offset: 0/32/64/96
    const int n0   = blockIdx.x * BN;
    const int m0   = blockIdx.y * BM;

    const int arow = tid & 127;
    const int ac8  = (tid >> 7) * 8;
    const int brow = tid >> 5;
    const int bc4  = (tid & 31) * 4;

    const float* Xa = X + (size_t)(m0 + arow) * DIM + ac8;
    const float* Wa = W + (size_t)brow * DIM + n0 + bc4;
    const float* Wb = W + (size_t)(brow + 8) * DIM + n0 + bc4;

    // fragment k rows for this thread
    const int k0 = 2 * tg;
    const int k1 = 2 * tg + 1;
    const int k2 = 2 * tg + 8;
    const int k3 = 2 * tg + 9;

    float acc[4][4][4];   // [mf][nf][c]
    #pragma unroll
    for (int i = 0; i < 4; i++)
        #pragma unroll
        for (int j = 0; j < 4; j++)
            #pragma unroll
            for (int c = 0; c < 4; c++)
                acc[i][j][c] = 0.f;

    float4 pa0 = *reinterpret_cast<const float4*>(Xa);
    float4 pa1 = *reinterpret_cast<const float4*>(Xa + 4);
    float4 pb0 = *reinterpret_cast<const float4*>(Wa);
    float4 pb1 = *reinterpret_cast<const float4*>(Wb);
    {
        float* A0 = As[0];
        A0[(ac8 + 0) * KPAD + arow] = pa0.x;
        A0[(ac8 + 1) * KPAD + arow] = pa0.y;
        A0[(ac8 + 2) * KPAD + arow] = pa0.z;
        A0[(ac8 + 3) * KPAD + arow] = pa0.w;
        A0[(ac8 + 4) * KPAD + arow] = pa1.x;
        A0[(ac8 + 5) * KPAD + arow] = pa1.y;
        A0[(ac8 + 6) * KPAD + arow] = pa1.z;
        A0[(ac8 + 7) * KPAD + arow] = pa1.w;
        *reinterpret_cast<float4*>(&Bs[0][brow * KPAD + bc4]) = pb0;
        *reinterpret_cast<float4*>(&Bs[0][(brow + 8) * KPAD + bc4]) = pb1;
    }
    __syncthreads();

    int buf = 0;
    for (int kk = 0; kk < DIM; kk += BK) {
        const bool more = (kk + BK < DIM);
        if (more) {
            pa0 = *reinterpret_cast<const float4*>(Xa + kk + BK);
            pa1 = *reinterpret_cast<const float4*>(Xa + kk + BK + 4);
            pb0 = *reinterpret_cast<const float4*>(Wa + (size_t)(kk + BK) * DIM);
            pb1 = *reinterpret_cast<const float4*>(Wb + (size_t)(kk + BK) * DIM);
        }

        const float* Ab = As[buf];
        const float* Bb = Bs[buf];

        // B fragments: 4 scalar LDS + split per nf (shared across all mf)
        uint32_t bhi[4][2], blo[4][2];
        #pragma unroll
        for (int nf = 0; nf < 4; nf++) {
            const int ncol = wn + nf * 8 + g;
            split2_f16(Bb[k0 * KPAD + ncol], Bb[k1 * KPAD + ncol],
                       bhi[nf][0], blo[nf][0]);
            split2_f16(Bb[k2 * KPAD + ncol], Bb[k3 * KPAD + ncol],
                       bhi[nf][1], blo[nf][1]);
        }
        // A fragments per mf, then 12 mma (3 terms x 4 nf)
        #pragma unroll
        for (int mf = 0; mf < 4; mf++) {
            const int mrow = wm + mf * 16 + g;
            uint32_t ahi[4], alo[4];
            split2_f16(Ab[k0 * KPAD + mrow],     Ab[k1 * KPAD + mrow],
                       ahi[0], alo[0]);
            split2_f16(Ab[k0 * KPAD + mrow + 8], Ab[k1 * KPAD + mrow + 8],
                       ahi[1], alo[1]);
            split2_f16(Ab[k2 * KPAD + mrow],     Ab[k3 * KPAD + mrow],
                       ahi[2], alo[2]);
            split2_f16(Ab[k2 * KPAD + mrow + 8], Ab[k3 * KPAD + mrow + 8],
                       ahi[3], alo[3]);
            #pragma unroll
            for (int nf = 0; nf < 4; nf++) {
                mma_f16(acc[mf][nf], ahi, bhi[nf]);
                mma_f16(acc[mf][nf], ahi, blo[nf]);
                mma_f16(acc[mf][nf], alo, bhi[nf]);
            }
        }

        if (more) {
            float* An = As[buf ^ 1];
            An[(ac8 + 0) * KPAD + arow] = pa0.x;
            An[(ac8 + 1) * KPAD + arow] = pa0.y;
            An[(ac8 + 2) * KPAD + arow] = pa0.z;
            An[(ac8 + 3) * KPAD + arow] = pa0.w;
            An[(ac8 + 4) * KPAD + arow] = pa1.x;
            An[(ac8 + 5) * KPAD + arow] = pa1.y;
            An[(ac8 + 6) * KPAD + arow] = pa1.z;
            An[(ac8 + 7) * KPAD + arow] = pa1.w;
            *reinterpret_cast<float4*>(&Bs[buf ^ 1][brow * KPAD + bc4]) = pb0;
            *reinterpret_cast<float4*>(&Bs[buf ^ 1][(brow + 8) * KPAD + bc4]) = pb1;
            __syncthreads();
            buf ^= 1;
        }
    }

    // Epilogue: C layout c0=(g,2t) c1=(g,2t+1) c2=(g+8,2t) c3=(g+8,2t+1)
    #pragma unroll
    for (int nf = 0; nf < 4; nf++) {
        const int col = n0 + wn + nf * 8 + 2 * tg;
        const float2 bv = *reinterpret_cast<const float2*>(bias + col);
        #pragma unroll
        for (int mf = 0; mf < 4; mf++) {
            const int row0 = m0 + wm + mf * 16 + g;
            float2 o0 = {acc[mf][nf][0] + bv.x, acc[mf][nf][1] + bv.y};
            float2 o1 = {acc[mf][nf][2] + bv.x, acc[mf][nf][3] + bv.y};
            *reinterpret_cast<float2*>(Y + (size_t)row0 * DIM + col) = o0;
            *reinterpret_cast<float2*>(Y + (size_t)(row0 + 8) * DIM + col) = o1;
        }
    }
}

// ---------------------------------------------------------------------------
// Attention: scores packed as fp16x2 in registers (64 regs vs 128),
// __launch_bounds__(256,2) -> 2 CTAs/SM, occ 12.5%->25%.
// coef/tbias folded at pack time so stored values are O(1) (fp16-safe).
// __expf guarantees MUFU fast path for the sigmoid.
// Structure otherwise identical to the verified R6 kernel.
// ---------------------------------------------------------------------------
extern __shared__ float dynsm[];

__global__ __launch_bounds__(256, 2) void attn_kernel(
    const float* __restrict__ Q, const float* __restrict__ Km,
    const float* __restrict__ Vm, float* __restrict__ att,
    const float* __restrict__ MW, const float* __restrict__ TSy,
    const int* __restrict__ qm_p, const int* __restrict__ km_p)
{
    float* const smA[2] = {dynsm, dynsm + TILE_F};
    float* const smB[2] = {dynsm + 2 * TILE_F, dynsm + 3 * TILE_F};

    const int tid = threadIdx.x;
    const int tx = tid & 15;   // key/d sub-tile
    const int ty = tid >> 4;   // query sub-tile
    const int qt = blockIdx.x;     // 0..7
    const int h  = blockIdx.y;     // 0..7
    const int bt = blockIdx.z;     // 0..31  (= b*16 + t)
    const int t  = bt & 15;

    const float* Qb = Q  + ((size_t)bt * 512 + qt * 64) * DIM + h * HDIM;
    const float* Kb = Km + (size_t)bt * 512 * DIM + h * HDIM;
    const float* Vb = Vm + (size_t)bt * 512 * DIM + h * HDIM;

    // scale/bias known up-front; folded into the packed scores
    const int qm = *qm_p;
    const int km = *km_p;
    const float coef  = MW[qm * NHEAD + h] * MW[km * NHEAD + h] * 0.125f; // /sqrt(64)
    const float tbias = TSy[t * NHEAD + h];

    const int lr = tid >> 2;          // 0..63
    const int lc = (tid & 3) * 16;    // 0,16,32,48

    // --- Prologue: Q^T into smA0, K chunk 0 (transposed) into smB0 ---
    #pragma unroll
    for (int u = 0; u < 4; u++) {
        float4 v = *reinterpret_cast<const float4*>(Qb + (size_t)lr * DIM + lc + u * 4);
        smA[0][(lc + u * 4 + 0) * TPAD + lr] = v.x;
        smA[0][(lc + u * 4 + 1) * TPAD + lr] = v.y;
        smA[0][(lc + u * 4 + 2) * TPAD + lr] = v.z;
        smA[0][(lc + u * 4 + 3) * TPAD + lr] = v.w;
    }
    float4 pf[4];
    #pragma unroll
    for (int u = 0; u < 4; u++)
        pf[u] = *reinterpret_cast<const float4*>(Kb + (size_t)lr * DIM + lc + u * 4);
    #pragma unroll
    for (int u = 0; u < 4; u++) {
        smB[0][(lc + u * 4 + 0) * TPAD + lr] = pf[u].x;
        smB[0][(lc + u * 4 + 1) * TPAD + lr] = pf[u].y;
        smB[0][(lc + u * 4 + 2) * TPAD + lr] = pf[u].z;
        smB[0][(lc + u * 4 + 3) * TPAD + lr] = pf[u].w;
    }
    __syncthreads();

    // packed scores: [chunk][row][key-pair]  (64 x 32-bit regs)
    __half2 sc16[8][4][2];

    // --- Phase 1: scores = Q @ K^T, double-buffered K chunks; pack per chunk ---
    #pragma unroll
    for (int c = 0; c < 8; c++) {
        if (c + 1 < 8) {
            #pragma unroll
            for (int u = 0; u < 4; u++)
                pf[u] = *reinterpret_cast<const float4*>(
                    Kb + (size_t)((c + 1) * 64 + lr) * DIM + lc + u * 4);
        }
        float s[4][4];
        #pragma unroll
        for (int i = 0; i < 4; i++)
            #pragma unroll
            for (int j = 0; j < 4; j++)
                s[i][j] = 0.f;

        const float* Bb = smB[c & 1];
        #pragma unroll 4
        for (int p = 0; p < 64; p++) {
            float4 a4 = *reinterpret_cast<const float4*>(&smA[0][p * TPAD + ty * 4]);
            float4 b4 = *reinterpret_cast<const float4*>(&Bb[p * TPAD + tx * 4]);
            float a_[4] = {a4.x, a4.y, a4.z, a4.w};
            float b_[4] = {b4.x, b4.y, b4.z, b4.w};
            #pragma unroll
            for (int i = 0; i < 4; i++)
                #pragma unroll
                for (int j = 0; j < 4; j++)
                    s[i][j] += a_[i] * b_[j];
        }
        // fold scale+bias, pack to fp16x2
        #pragma unroll
        for (int i = 0; i < 4; i++) {
            sc16[c][i][0] = __floats2half2_rn(s[i][0] * coef + tbias,
                                              s[i][1] * coef + tbias);
            sc16[c][i][1] = __floats2half2_rn(s[i][2] * coef + tbias,
                                              s[i][3] * coef + tbias);
        }
        if (c + 1 < 8) {
            float* Bn = smB[(c + 1) & 1];
            #pragma unroll
            for (int u = 0; u < 4; u++) {
                Bn[(lc + u * 4 + 0) * TPAD + lr] = pf[u].x;
                Bn[(lc + u * 4 + 1) * TPAD + lr] = pf[u].y;
                Bn[(lc + u * 4 + 2) * TPAD + lr] = pf[u].z;
                Bn[(lc + u * 4 + 3) * TPAD + lr] = pf[u].w;
            }
            __syncthreads();
        }
    }

    // --- Phase 2: sigmoid-softmax over 512 keys per query row (packed) ---
    #pragma unroll
    for (int i = 0; i < 4; i++) {
        float m = -1e30f;
        #pragma unroll
        for (int c = 0; c < 8; c++)
            #pragma unroll
            for (int jp = 0; jp < 2; jp++) {
                float2 v = __half22float2(sc16[c][i][jp]);
                m = fmaxf(m, fmaxf(v.x, v.y));
            }
        #pragma unroll
        for (int o = 8; o >= 1; o >>= 1)
            m = fmaxf(m, __shfl_xor_sync(0xffffffffu, m, o));
        float ssum = 0.f;
        #pragma unroll
        for (int c = 0; c < 8; c++)
            #pragma unroll
            for (int jp = 0; jp < 2; jp++) {
                float2 v = __half22float2(sc16[c][i][jp]);
                float p0 = 1.0f / (1.0f + __expf(-5.0f * (v.x - m)));
                float p1 = 1.0f / (1.0f + __expf(-5.0f * (v.y - m)));
                sc16[c][i][jp] = __floats2half2_rn(p0, p1);
                ssum += p0 + p1;
            }
        #pragma unroll
        for (int o = 8; o >= 1; o >>= 1)
            ssum += __shfl_xor_sync(0xffffffffu, ssum, o);
        const float inv = 1.0f / (ssum + 1e-8f);
        #pragma unroll
        for (int c = 0; c < 8; c++)
            #pragma unroll
            for (int jp = 0; jp < 2; jp++) {
                float2 v = __half22float2(sc16[c][i][jp]);
                sc16[c][i][jp] = __floats2half2_rn(v.x * inv, v.y * inv);
            }
    }

    // --- Phase 3: out = attn @ V, double-buffered P and V chunks ---
    #pragma unroll
    for (int u = 0; u < 4; u++)
        pf[u] = *reinterpret_cast<const float4*>(Vb + (size_t)lr * DIM + lc + u * 4);
    __syncthreads();   // all phase-1 reads of smA/smB complete before overwrite
    #pragma unroll
    for (int i = 0; i < 4; i++) {
        float2 v0 = __half22float2(sc16[0][i][0]);
        float2 v1 = __half22float2(sc16[0][i][1]);
        float* dst = &smA[0][(ty * 4 + i) * TPAD + tx * 4];
        dst[0] = v0.x;  dst[1] = v0.y;  dst[2] = v1.x;  dst[3] = v1.y;
    }
    #pragma unroll
    for (int u = 0; u < 4; u++)
        *reinterpret_cast<float4*>(&smB[0][lr * TPAD + lc + u * 4]) = pf[u];
    __syncthreads();

    float out[4][4] = {};
    #pragma unroll
    for (int c = 0; c < 8; c++) {
        if (c + 1 < 8) {
            #pragma unroll
            for (int u = 0; u < 4; u++)
                pf[u] = *reinterpret_cast<const float4*>(
                    Vb + (size_t)((c + 1) * 64 + lr) * DIM + lc + u * 4);
        }
        const float* Ab = smA[c & 1];
        const float* Bb = smB[c & 1];
        #pragma unroll 4
        for (int p = 0; p < 64; p++) {
            float a_[4];
            #pragma unroll
            for (int i = 0; i < 4; i++) a_[i] = Ab[(ty * 4 + i) * TPAD + p];
            float4 b4 = *reinterpret_cast<const float4*>(&Bb[p * TPAD + tx * 4]);
            float b_[4] = {b4.x, b4.y, b4.z, b4.w};
            #pragma unroll
            for (int i = 0; i < 4; i++)
                #pragma unroll
                for (int j = 0; j < 4; j++)
                    out[i][j] += a_[i] * b_[j];
        }
        if (c + 1 < 8) {
            float* An = smA[(c + 1) & 1];
            float* Bn = smB[(c + 1) & 1];
            #pragma unroll
            for (int i = 0; i < 4; i++) {
                float2 v0 = __half22float2(sc16[c + 1][i][0]);
                float2 v1 = __half22float2(sc16[c + 1][i][1]);
                float* dst = &An[(ty * 4 + i) * TPAD + tx * 4];
                dst[0] = v0.x;  dst[1] = v0.y;  dst[2] = v1.x;  dst[3] = v1.y;
            }
            #pragma unroll
            for (int u = 0; u < 4; u++)
                *reinterpret_cast<float4*>(&Bn[lr * TPAD + lc + u * 4]) = pf[u];
            __syncthreads();
        }
    }

    // Store attended tile
    #pragma unroll
    for (int i = 0; i < 4; i++) {
        float4 o = {out[i][0], out[i][1], out[i][2], out[i][3]};
        *reinterpret_cast<float4*>(
            att + ((size_t)bt * 512 + qt * 64 + ty * 4 + i) * DIM + h * HDIM + tx * 4) = o;
    }
}

// ---------------------------------------------------------------------------
// Launch
// Inputs (metadata order):
//  0 query_spikes [2,16,512,512] f32   1 key_spikes   2 value_spikes
//  3 Wq [512,512]  4 bq [512]  5 Wk  6 bk  7 Wv  8 bv  9 Wo  10 bo
//  11 modality_weights [2,8]  12 temporal_sync [16,8]
//  13 query_modality (int)   14 key_modality (int)
// Output: [2,16,512,512] f32
// ---------------------------------------------------------------------------
extern "C" void kernel_launch(void* const* d_in, const int* in_sizes, int n_in,
                              void* d_out, int out_size)
{
    (void)in_sizes; (void)n_in; (void)out_size;

    const float* qs = (const float*)d_in[0];
    const float* ks = (const float*)d_in[1];
    const float* vs = (const float*)d_in[2];
    const float* Wq = (const float*)d_in[3];
    const float* bq = (const float*)d_in[4];
    const float* Wk = (const float*)d_in[5];
    const float* bk = (const float*)d_in[6];
    const float* Wv = (const float*)d_in[7];
    const float* bv = (const float*)d_in[8];
    const float* Wo = (const float*)d_in[9];
    const float* bo = (const float*)d_in[10];
    const float* MW = (const float*)d_in[11];
    const float* TSy = (const float*)d_in[12];
    const int* qm = (const int*)d_in[13];
    const int* km = (const int*)d_in[14];
    float* out = (float*)d_out;

    // Device-global scratch pointers (symbol lookup: not a stream op, capture-safe)
    void *pQ, *pK, *pV, *pA;
    cudaGetSymbolAddress(&pQ, g_Q);
    cudaGetSymbolAddress(&pK, g_K);
    cudaGetSymbolAddress(&pV, g_V);
    cudaGetSymbolAddress(&pA, g_att);
    float* gQ = (float*)pQ;
    float* gK = (float*)pK;
    float* gV = (float*)pV;
    float* gA = (float*)pA;

    // Unconditional (idempotent, host-side, not a stream op — capture-safe)
    const int attn_smem = 4 * TILE_F * sizeof(float);   // 69632 B
    cudaFuncSetAttribute(attn_kernel,
                         cudaFuncAttributeMaxDynamicSharedMemorySize, attn_smem);

    dim3 gemm_grid(DIM / BN, M_ROWS / BM);   // (4, 128)
    dim3 attn_grid(8, NHEAD, 32);            // q-tiles, heads, b*t

    gemm_f16split_kernel<<<gemm_grid, 256>>>(qs, Wq, bq, gQ);
    gemm_f16split_kernel<<<gemm_grid, 256>>>(ks, Wk, bk, gK);
    gemm_f16split_kernel<<<gemm_grid, 256>>>(vs, Wv, bv, gV);
    attn_kernel<<<attn_grid, 256, attn_smem>>>(gQ, gK, gV, gA, MW, TSy, qm, km);
    gemm_f16split_kernel<<<gemm_grid, 256>>>(gA, Wo, bo, out);
}